// round 5
// baseline (speedup 1.0000x reference)
#include <cuda_runtime.h>
#include <cstdint>

#define BS     128
#define HW     256
#define NPX    65536                       // HW*HW
#define NTOT   (BS * NPX)                  // 8,388,608
#define CHUNK  1024                        // pixels per work item
#define CPB    (NPX / CHUNK)               // 64 chunks per batch
#define LAG    6                           // batch lag between pipeline stages
#define NROUNDS (BS + 2 * LAG)             // 140
#define ITEMS_PER_ROUND (3 * CPB)          // 192
#define TOTAL_ITEMS (NROUNDS * ITEMS_PER_ROUND)

// Scratch + pipeline state
__device__ int      g_keys[NTOT];          // 33.5 MB scatter keys (winner = max p)
__device__ int      g_nvalid[BS];
__device__ int      g_prep_done[BS];
__device__ int      g_scat_done[BS];
__device__ unsigned g_work;

// ---------------------------------------------------------------------------
__global__ void k_init() {
    int t = threadIdx.x;
    if (t < BS) { g_nvalid[t] = 0; g_prep_done[t] = 0; g_scat_done[t] = 0; }
    if (t == 0) g_work = 0u;
}

// producer: all threads fence their writes, then thread0 bumps the flag
__device__ __forceinline__ void signal_done(int* flag) {
    __threadfence();
    __syncthreads();
    if (threadIdx.x == 0) atomicAdd(flag, 1);
}

// consumer: thread0 spins, then block-wide fence before consuming
__device__ __forceinline__ void wait_count(int* flag, int target) {
    if (threadIdx.x == 0) {
        while (__ldcg((const int*)flag) < target) __nanosleep(64);
        __threadfence();
    }
    __syncthreads();
    __threadfence();
}

// ---------------------------------------------------------------------------
// Persistent pipelined kernel. Item schedule per round r:
//   [64x prep(b=r)] [64x scatter(b=r-LAG)] [64x gather(b=r-2*LAG)]
// ---------------------------------------------------------------------------
__global__ void __launch_bounds__(256)
k_pipe(const float* __restrict__ grid, const float* __restrict__ seg,
       const float* __restrict__ conf, const float* __restrict__ depth,
       float* __restrict__ out) {
    __shared__ int s_item;
    __shared__ int s_red[8];
    const int tid = threadIdx.x;

    for (;;) {
        __syncthreads();                       // protect s_item reuse
        if (tid == 0) s_item = (int)atomicAdd(&g_work, 1u);
        __syncthreads();
        int item = s_item;
        if (item >= TOTAL_ITEMS) return;

        int r     = item / ITEMS_PER_ROUND;
        int pos   = item % ITEMS_PER_ROUND;
        int phase = pos / CPB;                 // 0=prep 1=scatter 2=gather
        int c     = pos % CPB;
        int b     = r - phase * LAG;
        if (b < 0 || b >= BS) continue;        // schedule padding

        int base = b * NPX + c * CHUNK;        // global pixel base of item
        int i4   = (base >> 2) + tid;          // float4/int4 index (4 px/thread)

        if (phase == 0) {
            // ---- prep: zero 1024 keys + count seg>0.5 -------------------
            reinterpret_cast<int4*>(g_keys)[i4] = make_int4(0, 0, 0, 0);
            float4 v = reinterpret_cast<const float4*>(seg)[i4];
            int cnt = (v.x > 0.5f) + (v.y > 0.5f) + (v.z > 0.5f) + (v.w > 0.5f);
            #pragma unroll
            for (int o = 16; o; o >>= 1) cnt += __shfl_down_sync(0xFFFFFFFFu, cnt, o);
            if ((tid & 31) == 0) s_red[tid >> 5] = cnt;
            __syncthreads();
            if (tid == 0) {
                int t = 0;
                #pragma unroll
                for (int j = 0; j < 8; j++) t += s_red[j];
                atomicAdd(&g_nvalid[b], t);
            }
            signal_done(&g_prep_done[b]);

        } else if (phase == 1) {
            // ---- scatter: atomicMax(key) for valid px; dedup hot cell ---
            wait_count(&g_prep_done[b], CPB);
            bool fb = (__ldcg(&g_nvalid[b]) == 0);

            float4 sg = reinterpret_cast<const float4*>(seg)[i4];
            size_t gb4 = ((size_t)b * 2 * NPX + c * CHUNK) / 4 + tid;
            float4 gx = __ldcs(reinterpret_cast<const float4*>(grid) + gb4);
            float4 gy = __ldcs(reinterpret_cast<const float4*>(grid) + gb4 + NPX / 4);

            int p0 = c * CHUNK + tid * 4;      // within-batch pixel index
            float xs[4] = {gx.x, gx.y, gx.z, gx.w};
            float ys[4] = {gy.x, gy.y, gy.z, gy.w};
            float ss[4] = {sg.x, sg.y, sg.z, sg.w};
            int localmax = -1;
            #pragma unroll
            for (int j = 0; j < 4; j++) {
                bool m = fb || (ss[j] > 0.5f);
                if (m) {
                    // exact pow2 scaling: ((g+1)*0.5)*256, trunc, clip
                    int ix = (int)(((xs[j] + 1.0f) * 0.5f) * 256.0f);
                    int iy = (int)(((ys[j] + 1.0f) * 0.5f) * 256.0f);
                    ix = min(max(ix, 0), HW - 1);
                    iy = min(max(iy, 0), HW - 1);
                    atomicMax(&g_keys[(b << 16) + (iy << 8) + ix], p0 + j);
                } else {
                    localmax = p0 + j;         // masked px all target (128,128)
                }
            }
            int wm = __reduce_max_sync(0xFFFFFFFFu, localmax);
            if ((tid & 31) == 0) s_red[tid >> 5] = wm;
            __syncthreads();
            if (tid == 0) {
                int mx = -1;
                #pragma unroll
                for (int j = 0; j < 8; j++) mx = max(mx, s_red[j]);
                if (mx >= 0)
                    atomicMax(&g_keys[(b << 16) + (128 << 8) + 128], mx);
            }
            signal_done(&g_scat_done[b]);

        } else {
            // ---- gather: key -> nearest src (h&~1, w&~1), write 5 planes -
            wait_count(&g_scat_done[b], CPB);
            bool fb = (__ldcg(&g_nvalid[b]) == 0);

            int4 key = __ldcg(reinterpret_cast<const int4*>(g_keys) + i4);
            int keys[4] = {key.x, key.y, key.z, key.w};
            float rx[4], ry[4], rd[4], rc[4], rm[4];
            #pragma unroll
            for (int j = 0; j < 4; j++) {
                int k  = keys[j];
                int sx = k & 254;              // (k&255) & ~1
                int sy = (k >> 8) & 254;
                int sidx = (b << 16) + (sy << 8) + sx;
                float m = (fb || __ldg(seg + sidx) > 0.5f) ? 1.0f : 0.0f;
                rd[j] = __ldg(depth + sidx) * m;
                rc[j] = __ldg(conf + sidx);
                rx[j] = (float)sx * (1.0f / 280.0f) * m;
                ry[j] = (float)sy * (1.0f / 280.0f) * m;
                rm[j] = m;
            }
            float* dk = out;                                 // [BS,3,HW,HW]
            float* cf = out + (size_t)BS * 3 * NPX;          // [BS,1,HW,HW]
            float* mk = cf  + (size_t)BS * NPX;              // [BS,HW,HW]
            size_t db4 = ((size_t)b * 3 * NPX + c * CHUNK) / 4 + tid;
            __stcs(reinterpret_cast<float4*>(dk) + db4,
                   make_float4(rx[0], rx[1], rx[2], rx[3]));
            __stcs(reinterpret_cast<float4*>(dk) + db4 + NPX / 4,
                   make_float4(ry[0], ry[1], ry[2], ry[3]));
            __stcs(reinterpret_cast<float4*>(dk) + db4 + NPX / 2,
                   make_float4(rd[0], rd[1], rd[2], rd[3]));
            __stcs(reinterpret_cast<float4*>(cf) + i4,
                   make_float4(rc[0], rc[1], rc[2], rc[3]));
            __stcs(reinterpret_cast<float4*>(mk) + i4,
                   make_float4(rm[0], rm[1], rm[2], rm[3]));
        }
    }
}

// ---------------------------------------------------------------------------
extern "C" void kernel_launch(void* const* d_in, const int* in_sizes, int n_in,
                              void* d_out, int out_size) {
    const float* grid    = (const float*)d_in[0];
    const float* seg     = (const float*)d_in[1];
    const float* conf_is = (const float*)d_in[2];
    const float* depth   = (const float*)d_in[3];
    float* out = (float*)d_out;
    (void)in_sizes; (void)n_in; (void)out_size;

    k_init<<<1, 256>>>();
    k_pipe<<<1024, 256>>>(grid, seg, conf_is, depth, out);
}

// round 8
// speedup vs baseline: 1.8676x; 1.8676x over previous
#include <cuda_runtime.h>
#include <cstdint>

#define BS   128
#define HW   256
#define NPX  65536                 // HW*HW
#define NTOT (BS * NPX)            // 8,388,608
#define NEVEN (128 * 128)          // even-coord sites per batch

// Scratch
__device__ int      g_keys[NTOT];               // 33.5 MB winner = max p (h*256+w)
__device__ float4   g_pack[BS * NEVEN];         // 33.5 MB {m, conf, depth, 0} at even sites
__device__ unsigned g_mbits[NTOT / 32];         // 1 MB seg>0.5 bitmap
__device__ int      g_nvalid[BS];

// bitmap layout: for pixel p (within batch b, global idx = b*NPX+p):
//   word = (gidx>>7)*4 + (p&3) ... we use: group g = gidx>>7 (128 px), words 4g..4g+3
//   word 4g+j holds bit 'lane' for pixel gidx = g*128 + lane*4 + j

// ---------------------------------------------------------------------------
// k1: zero keys + count + bitmap + packed even-site table
//     8192 blocks x 256 thr; thread t handles 4 px (float4/int4 index i4 = t)
// ---------------------------------------------------------------------------
__global__ void __launch_bounds__(256)
k_prep(const float* __restrict__ seg, const float* __restrict__ conf,
       const float* __restrict__ depth) {
    int i4 = blockIdx.x * blockDim.x + threadIdx.x;     // 0 .. NTOT/4
    int lane = threadIdx.x & 31;

    reinterpret_cast<int4*>(g_keys)[i4] = make_int4(0, 0, 0, 0);

    float4 s = reinterpret_cast<const float4*>(seg)[i4];
    bool m0 = s.x > 0.5f, m1 = s.y > 0.5f, m2 = s.z > 0.5f, m3 = s.w > 0.5f;

    unsigned b0 = __ballot_sync(0xFFFFFFFFu, m0);
    unsigned b1 = __ballot_sync(0xFFFFFFFFu, m1);
    unsigned b2 = __ballot_sync(0xFFFFFFFFu, m2);
    unsigned b3 = __ballot_sync(0xFFFFFFFFu, m3);

    int g = i4 >> 5;                                    // 128-px group index
    if (lane == 0) {
        uint4 w = make_uint4(b0, b1, b2, b3);
        reinterpret_cast<uint4*>(g_mbits)[g] = w;
    }

    // per-block count -> one atomicAdd (block spans 1024 px, single batch)
    __shared__ int s_red[8];
    if (lane == 0)
        s_red[threadIdx.x >> 5] = __popc(b0) + __popc(b1) + __popc(b2) + __popc(b3);
    __syncthreads();
    if (threadIdx.x == 0) {
        int t = 0;
        #pragma unroll
        for (int j = 0; j < 8; j++) t += s_red[j];
        atomicAdd(&g_nvalid[(i4 * 4) >> 16], t);
    }

    // packed even-site table: warp covers 128 contiguous px = half a row,
    // so h is uniform per warp. Even-h warps write sites (h/2, w/2), (h/2, w/2+1).
    int p = (i4 << 2) & 0xFFFF;                         // within-batch pixel
    int h = p >> 8;
    if ((h & 1) == 0) {
        float4 c = __ldcs(reinterpret_cast<const float4*>(conf) + i4);
        float4 d = __ldcs(reinterpret_cast<const float4*>(depth) + i4);
        int b = (i4 << 2) >> 16;
        int w = p & 255;                                // 4t mod 256, even
        int site = b * NEVEN + (h >> 1) * 128 + (w >> 1);
        g_pack[site]     = make_float4(m0 ? 1.0f : 0.0f, c.x, d.x, 0.0f);
        g_pack[site + 1] = make_float4(m2 ? 1.0f : 0.0f, c.z, d.z, 0.0f);
    }
}

// ---------------------------------------------------------------------------
// k2: scatter, 4 px/thread. atomicMax(key, p) for valid px; masked px all
//     target (b,128,128): block-dedup to ONE atomic.
// ---------------------------------------------------------------------------
__global__ void __launch_bounds__(256)
k_scatter(const float* __restrict__ grid) {
    int i4 = blockIdx.x * blockDim.x + threadIdx.x;
    int gidx = i4 << 2;
    int b = gidx >> 16;
    int p0 = gidx & 0xFFFF;
    int lane = threadIdx.x & 31;

    bool fb = (__ldg(&g_nvalid[b]) == 0);

    uint4 mb = reinterpret_cast<const uint4*>(g_mbits)[i4 >> 5];   // warp-broadcast
    unsigned mw[4] = {mb.x, mb.y, mb.z, mb.w};

    size_t gb4 = ((size_t)b * 2 * NPX + p0) >> 2;
    float4 gx = __ldcs(reinterpret_cast<const float4*>(grid) + gb4);
    float4 gy = __ldcs(reinterpret_cast<const float4*>(grid) + gb4 + NPX / 4);

    float xs[4] = {gx.x, gx.y, gx.z, gx.w};
    float ys[4] = {gy.x, gy.y, gy.z, gy.w};
    int localmax = -1;
    #pragma unroll
    for (int j = 0; j < 4; j++) {
        bool m = fb || ((mw[j] >> lane) & 1u);
        if (m) {
            // exact pow2 scaling: ((g+1)*0.5)*256, trunc toward zero, clip
            int ix = (int)(((xs[j] + 1.0f) * 0.5f) * 256.0f);
            int iy = (int)(((ys[j] + 1.0f) * 0.5f) * 256.0f);
            ix = min(max(ix, 0), HW - 1);
            iy = min(max(iy, 0), HW - 1);
            atomicMax(&g_keys[(b << 16) + (iy << 8) + ix], p0 + j);
        } else {
            localmax = p0 + j;            // masked px target (128,128)
        }
    }
    int wm = __reduce_max_sync(0xFFFFFFFFu, localmax);
    __shared__ int s_red[8];
    if (lane == 0) s_red[threadIdx.x >> 5] = wm;
    __syncthreads();
    if (threadIdx.x == 0) {
        int mx = -1;
        #pragma unroll
        for (int j = 0; j < 8; j++) mx = max(mx, s_red[j]);
        if (mx >= 0)
            atomicMax(&g_keys[(b << 16) + (128 << 8) + 128], mx);
    }
}

// ---------------------------------------------------------------------------
// k3: gather, 4 px/thread. key -> even site (h&~1, w&~1); ONE packed float4
//     scattered load per px; write 5 output planes with __stcs.
// ---------------------------------------------------------------------------
__global__ void __launch_bounds__(256)
k_gather(float* __restrict__ out) {
    int t = blockIdx.x * blockDim.x + threadIdx.x;      // int4 index
    int gidx = t << 2;
    int b = gidx >> 16;

    bool fb = (__ldg(&g_nvalid[b]) == 0);
    int4 key = reinterpret_cast<const int4*>(g_keys)[t];

    int keys[4] = {key.x, key.y, key.z, key.w};
    float rx[4], ry[4], rd[4], rc[4], rm[4];
    #pragma unroll
    for (int j = 0; j < 4; j++) {
        int k  = keys[j];
        int sx = k & 254;                 // even col
        int sy = (k >> 8) & 254;          // even row
        float4 pk = __ldg(&g_pack[b * NEVEN + (sy >> 1) * 128 + (sx >> 1)]);
        float m = fb ? 1.0f : pk.x;
        rd[j] = pk.z * m;
        rc[j] = pk.y;
        rx[j] = (float)sx * (1.0f / 280.0f) * m;
        ry[j] = (float)sy * (1.0f / 280.0f) * m;
        rm[j] = m;
    }

    float* dk = out;                                 // [BS,3,HW,HW]
    float* cf = out + (size_t)BS * 3 * NPX;          // [BS,1,HW,HW]
    float* mk = cf  + (size_t)BS * NPX;              // [BS,HW,HW]
    int p0 = gidx & 0xFFFF;
    size_t db4 = ((size_t)b * 3 * NPX + p0) >> 2;
    __stcs(reinterpret_cast<float4*>(dk) + db4,
           make_float4(rx[0], rx[1], rx[2], rx[3]));
    __stcs(reinterpret_cast<float4*>(dk) + db4 + NPX / 4,
           make_float4(ry[0], ry[1], ry[2], ry[3]));
    __stcs(reinterpret_cast<float4*>(dk) + db4 + NPX / 2,
           make_float4(rd[0], rd[1], rd[2], rd[3]));
    __stcs(reinterpret_cast<float4*>(cf) + t,
           make_float4(rc[0], rc[1], rc[2], rc[3]));
    __stcs(reinterpret_cast<float4*>(mk) + t,
           make_float4(rm[0], rm[1], rm[2], rm[3]));
}

// ---------------------------------------------------------------------------
extern "C" void kernel_launch(void* const* d_in, const int* in_sizes, int n_in,
                              void* d_out, int out_size) {
    const float* grid    = (const float*)d_in[0];
    const float* seg     = (const float*)d_in[1];
    const float* conf_is = (const float*)d_in[2];
    const float* depth   = (const float*)d_in[3];
    float* out = (float*)d_out;
    (void)in_sizes; (void)n_in; (void)out_size;

    cudaMemsetAsync(g_nvalid, 0, sizeof(int) * BS);
    k_prep<<<NTOT / 4 / 256, 256>>>(seg, conf_is, depth);
    k_scatter<<<NTOT / 4 / 256, 256>>>(grid);
    k_gather<<<NTOT / 4 / 256, 256>>>(out);
}